// round 1
// baseline (speedup 1.0000x reference)
#include <cuda_runtime.h>
#include <cstdint>

#define C_IN   256
#define C_OUT  256
#define HDIM   56
#define WDIM   56
#define BATCH  32
#define HW     (HDIM*WDIM)        // 3136
#define ROWS   14                 // rows per conv tile
#define NPIX   (BATCH*HW)         // 100352

// Scratch (no allocations allowed)
__device__ uint32_t g_abits[NPIX * 8];        // [b][h][w][cw]  3.2 MB
__device__ uint32_t g_wbits[9 * 8 * C_OUT];   // [tap][cw][co]  73 KB
__device__ float    g_sa[C_OUT];              // alpha[co]*scale[co]

// ---------------------------------------------------------------------------
// 1) Weight prep: real_w = sum_k RV[k]*W[k]; scale = mean|real_w|; pack signs.
//    One block per output channel, thread = ci.
// ---------------------------------------------------------------------------
__global__ void prep_weights(const float* __restrict__ W,
                             const float* __restrict__ RV,
                             const float* __restrict__ alpha) {
    const int co = blockIdx.x;
    const int ci = threadIdx.x;
    const float r0 = RV[0], r1 = RV[1], r2 = RV[2], r3 = RV[3];
    const int stride_k = C_OUT * C_IN * 9;
    const float* base = W + ((size_t)co * C_IN + ci) * 9;
    const int warp = ci >> 5;

    float asum = 0.f;
#pragma unroll
    for (int tap = 0; tap < 9; ++tap) {
        float v = r0 * base[tap]
                + r1 * base[stride_k + tap]
                + r2 * base[2 * stride_k + tap]
                + r3 * base[3 * stride_k + tap];
        asum += fabsf(v);
        unsigned m = __ballot_sync(0xffffffffu, v >= 0.f);
        if ((ci & 31) == 0) g_wbits[(tap * 8 + warp) * C_OUT + co] = m;
    }

    __shared__ float red[256];
    red[ci] = asum;
    __syncthreads();
    for (int s = 128; s > 0; s >>= 1) {
        if (ci < s) red[ci] += red[ci + s];
        __syncthreads();
    }
    if (ci == 0) g_sa[co] = alpha[co] * (red[0] * (1.0f / 2304.0f));
}

// ---------------------------------------------------------------------------
// 2) Activation pack: bit cw*32+t of pixel word = (x[b, ci, h, w] >= 0).
//    Thread = one pixel; loads coalesced across lanes (consecutive w).
// ---------------------------------------------------------------------------
__global__ void pack_act(const float* __restrict__ x) {
    const int pix = blockIdx.x * blockDim.x + threadIdx.x;
    if (pix >= NPIX) return;
    const int b = pix / HW;
    const int hw = pix % HW;
    const float* xp = x + (size_t)b * C_IN * HW + hw;

    uint32_t w[8];
#pragma unroll
    for (int j = 0; j < 8; ++j) {
        uint32_t word = 0;
#pragma unroll
        for (int t = 0; t < 32; ++t) {
            float v = __ldg(xp + (size_t)(j * 32 + t) * HW);
            word |= (v >= 0.f ? 1u : 0u) << t;
        }
        w[j] = word;
    }
    uint4* dst = reinterpret_cast<uint4*>(&g_abits[(size_t)pix * 8]);
    dst[0] = make_uint4(w[0], w[1], w[2], w[3]);
    dst[1] = make_uint4(w[4], w[5], w[6], w[7]);
}

// ---------------------------------------------------------------------------
// 3) XNOR conv. CTA = (image, 14-row band) x all 256 output channels.
//    Thread = co: 72 weight words in registers, activation words broadcast
//    from smem (uniform address LDS.128). Output staged via smem so the
//    global store is coalesced along pixels.
// ---------------------------------------------------------------------------
#define SMEM_A_WORDS ((ROWS + 2) * WDIM * 8)     // 7168 words
#define SMEM_BYTES   (SMEM_A_WORDS * 4 + 256 * 33 * 4)

__global__ void __launch_bounds__(256, 1) conv_kernel(float* __restrict__ out) {
    extern __shared__ uint32_t smem[];
    uint32_t* s_a   = smem;                                      // [16][56][8]
    float*    s_out = reinterpret_cast<float*>(smem + SMEM_A_WORDS); // [256][33]

    const int tile = blockIdx.x;
    const int b    = tile >> 2;
    const int row0 = (tile & 3) * ROWS;
    const int tid  = threadIdx.x;
    const int co   = tid;

    // Load activation band (with halo rows) into smem. Out-of-range rows are
    // left as garbage; never read (guarded by tap validity).
    {
        const uint4* src = reinterpret_cast<const uint4*>(g_abits);
        uint4* dst = reinterpret_cast<uint4*>(s_a);
        for (int i = tid; i < (ROWS + 2) * WDIM * 2; i += 256) {
            int r  = i / (WDIM * 2);
            int gh = row0 - 1 + r;
            if ((unsigned)gh < HDIM) {
                int rem = i - r * (WDIM * 2);
                dst[i] = src[(size_t)(b * HW + gh * WDIM) * 2 + rem];
            }
        }
    }

    // Per-thread weights (9 taps x 8 words), coalesced loads.
    uint32_t wreg[72];
#pragma unroll
    for (int i = 0; i < 72; ++i) wreg[i] = __ldg(&g_wbits[i * C_OUT + co]);
    const float sa = g_sa[co];
    __syncthreads();

    const uint4* s_a4 = reinterpret_cast<const uint4*>(s_a);
    float* outbase = out + (size_t)(b * C_OUT) * HW + row0 * WDIM;

    const int npix = ROWS * WDIM;                 // 784
    for (int lp0 = 0; lp0 < npix; lp0 += 32) {
        const int cnt = min(32, npix - lp0);
        for (int q = 0; q < cnt; ++q) {
            const int lp = lp0 + q;
            const int lr = lp / WDIM;
            const int c  = lp - lr * WDIM;
            const int h  = row0 + lr;
            int acc = 0;

            if (h > 0 && h < HDIM - 1 && c > 0 && c < WDIM - 1) {
                // interior fast path: all 9 taps valid, no guards
#pragma unroll
                for (int tap = 0; tap < 9; ++tap) {
                    const int dh = tap / 3 - 1, dw = tap % 3 - 1;
                    const int idx = ((lr + 1 + dh) * WDIM + (c + dw)) * 2;
                    uint4 a0 = s_a4[idx];
                    uint4 a1 = s_a4[idx + 1];
                    acc += __popc(a0.x ^ wreg[tap * 8 + 0])
                         + __popc(a0.y ^ wreg[tap * 8 + 1])
                         + __popc(a0.z ^ wreg[tap * 8 + 2])
                         + __popc(a0.w ^ wreg[tap * 8 + 3])
                         + __popc(a1.x ^ wreg[tap * 8 + 4])
                         + __popc(a1.y ^ wreg[tap * 8 + 5])
                         + __popc(a1.z ^ wreg[tap * 8 + 6])
                         + __popc(a1.w ^ wreg[tap * 8 + 7]);
                }
                s_out[co * 33 + q] = sa * (float)(2304 - 2 * acc);
            } else {
                int V = 0;
#pragma unroll
                for (int tap = 0; tap < 9; ++tap) {
                    const int dh = tap / 3 - 1, dw = tap % 3 - 1;
                    if ((unsigned)(h + dh) < HDIM && (unsigned)(c + dw) < WDIM) {
                        const int idx = ((lr + 1 + dh) * WDIM + (c + dw)) * 2;
                        uint4 a0 = s_a4[idx];
                        uint4 a1 = s_a4[idx + 1];
                        acc += __popc(a0.x ^ wreg[tap * 8 + 0])
                             + __popc(a0.y ^ wreg[tap * 8 + 1])
                             + __popc(a0.z ^ wreg[tap * 8 + 2])
                             + __popc(a0.w ^ wreg[tap * 8 + 3])
                             + __popc(a1.x ^ wreg[tap * 8 + 4])
                             + __popc(a1.y ^ wreg[tap * 8 + 5])
                             + __popc(a1.z ^ wreg[tap * 8 + 6])
                             + __popc(a1.w ^ wreg[tap * 8 + 7]);
                        ++V;
                    }
                }
                s_out[co * 33 + q] = sa * (float)(256 * V - 2 * acc);
            }
        }
        __syncthreads();
        // Coalesced store: lanes sweep pixels for each channel row.
        for (int i = tid; i < 256 * cnt; i += 256) {
            int p  = i % cnt;
            int cr = i / cnt;
            outbase[(size_t)cr * HW + lp0 + p] = s_out[cr * 33 + p];
        }
        __syncthreads();
    }
}

// ---------------------------------------------------------------------------
extern "C" void kernel_launch(void* const* d_in, const int* in_sizes, int n_in,
                              void* d_out, int out_size) {
    const float* x      = (const float*)d_in[0];
    const float* W      = (const float*)d_in[1];
    const float* RV     = (const float*)d_in[2];
    const float* alpha  = (const float*)d_in[3];
    float* out          = (float*)d_out;

    static_assert(SMEM_BYTES <= 227 * 1024, "smem");
    cudaFuncSetAttribute(conv_kernel,
                         cudaFuncAttributeMaxDynamicSharedMemorySize, SMEM_BYTES);

    prep_weights<<<C_OUT, 256>>>(W, RV, alpha);
    pack_act<<<(NPIX + 127) / 128, 128>>>(x);
    conv_kernel<<<BATCH * (HDIM / ROWS), 256, SMEM_BYTES>>>(out);
}

// round 3
// speedup vs baseline: 2.2444x; 2.2444x over previous
#include <cuda_runtime.h>
#include <cstdint>

#define C_IN   256
#define C_OUT  256
#define HDIM   56
#define WDIM   56
#define BATCH  32
#define HW     (HDIM*WDIM)        // 3136
#define PG     64                 // padded grid stride (64x64 per image)
#define GUARD  64
#define NVEC   (GUARD + BATCH*PG*PG + GUARD)   // 131200 activation vectors

// ---------------- scratch (no allocations allowed) ----------------
__device__ __align__(128) int8_t g_P[(size_t)NVEC * C_IN];      // padded +-1 acts, 33.6 MB
__device__ __align__(128) int8_t g_WB[9 * C_OUT * C_IN];        // +-1 weights [tap][co][ci]
__device__ float g_sa[C_OUT];                                   // alpha*scale

// ---------------------------------------------------------------------------
// 1) Weight prep
// ---------------------------------------------------------------------------
__global__ void prep_weights(const float* __restrict__ W,
                             const float* __restrict__ RV,
                             const float* __restrict__ alpha) {
    const int co = blockIdx.x;
    const int ci = threadIdx.x;
    const float r0 = RV[0], r1 = RV[1], r2 = RV[2], r3 = RV[3];
    const int sk = C_OUT * C_IN * 9;
    const float* base = W + ((size_t)co * C_IN + ci) * 9;

    float asum = 0.f;
#pragma unroll
    for (int tap = 0; tap < 9; ++tap) {
        float v = r0 * base[tap] + r1 * base[sk + tap]
                + r2 * base[2 * sk + tap] + r3 * base[3 * sk + tap];
        asum += fabsf(v);
        g_WB[((size_t)tap * C_OUT + co) * C_IN + ci] = (v >= 0.f) ? 1 : -1;
    }
    __shared__ float red[256];
    red[ci] = asum;
    __syncthreads();
    for (int s = 128; s > 0; s >>= 1) {
        if (ci < s) red[ci] += red[ci + s];
        __syncthreads();
    }
    if (ci == 0) g_sa[co] = alpha[co] * (red[0] * (1.0f / 2304.0f));
}

// ---------------------------------------------------------------------------
// 2) Activation pack: P[vec][ci] = sign(x) as int8 +-1 inside image, 0 outside.
//    vec = GUARD + b*4096 + r*64 + c; image occupies r,c in [1,56].
// ---------------------------------------------------------------------------
__global__ void pack_P(const float* __restrict__ x) {
    const int v = blockIdx.x * blockDim.x + threadIdx.x;
    if (v >= NVEC) return;
    const int vi = v - GUARD;
    bool img = false;
    int b = 0, h = 0, w = 0;
    if (vi >= 0 && vi < BATCH * PG * PG) {
        b = vi >> 12;
        const int r = (vi >> 6) & 63, c = vi & 63;
        if (r >= 1 && r <= 56 && c >= 1 && c <= 56) { img = true; h = r - 1; w = c - 1; }
    }
    uint4* dst = reinterpret_cast<uint4*>(g_P + (size_t)v * 256);
    if (!img) {
        const uint4 z = make_uint4(0, 0, 0, 0);
#pragma unroll
        for (int i = 0; i < 16; ++i) dst[i] = z;
    } else {
        const float* xp = x + (size_t)b * C_IN * HW + h * WDIM + w;
#pragma unroll
        for (int i = 0; i < 16; ++i) {
            uint32_t pk[4];
#pragma unroll
            for (int j = 0; j < 4; ++j) {
                uint32_t word = 0;
#pragma unroll
                for (int t = 0; t < 4; ++t) {
                    float vv = __ldg(xp + (size_t)(i * 16 + j * 4 + t) * HW);
                    word |= (uint32_t)((vv >= 0.f) ? 0x01u : 0xFFu) << (8 * t);
                }
                pk[j] = word;
            }
            dst[i] = make_uint4(pk[0], pk[1], pk[2], pk[3]);
        }
    }
}

// ---------------------------------------------------------------------------
// 3) Implicit-GEMM conv via mma.sync m16n8k32 s8 (sm_100-safe).
//    Tile: 128 pixels (2 padded rows) x 256 co. A-union (258 vectors) loaded
//    once; per-tap A windows are offsets into it. B double-buffered per tap.
// ---------------------------------------------------------------------------
#define AU_ROWS 258
#define SM_A    (260 * 256)            // 66560 B (rounded)
#define SM_B    65536                  // 256 co x 256 ci int8
#define SMEM_TOTAL (SM_A + 2 * SM_B)   // 197632 B

static __device__ __forceinline__ uint32_t su32(const void* p) {
    return (uint32_t)__cvta_generic_to_shared(p);
}
static __device__ __forceinline__ uint32_t swz(uint32_t row, uint32_t g) {
    return (g & 8u) | ((g ^ row) & 7u);
}
static __device__ __forceinline__ void cpa16(uint32_t dst, const void* src) {
    asm volatile("cp.async.cg.shared.global [%0], [%1], 16;" :: "r"(dst), "l"(src));
}
static __device__ __forceinline__ void ldm4(uint32_t& r0, uint32_t& r1,
                                            uint32_t& r2, uint32_t& r3, uint32_t a) {
    asm volatile("ldmatrix.sync.aligned.m8n8.x4.shared.b16 {%0,%1,%2,%3}, [%4];"
                 : "=r"(r0), "=r"(r1), "=r"(r2), "=r"(r3) : "r"(a));
}
static __device__ __forceinline__ void mma8(int* d, const uint32_t* a,
                                            uint32_t b0, uint32_t b1) {
    asm volatile(
        "mma.sync.aligned.m16n8k32.row.col.s32.s8.s8.s32 "
        "{%0,%1,%2,%3}, {%4,%5,%6,%7}, {%8,%9}, {%0,%1,%2,%3};"
        : "+r"(d[0]), "+r"(d[1]), "+r"(d[2]), "+r"(d[3])
        : "r"(a[0]), "r"(a[1]), "r"(a[2]), "r"(a[3]), "r"(b0), "r"(b1));
}

__global__ void __launch_bounds__(256, 1) conv_mma(float* __restrict__ out) {
    extern __shared__ __align__(1024) char smem[];
    const uint32_t Abase = su32(smem);
    const uint32_t Bbase = Abase + SM_A;

    const int tid  = threadIdx.x;
    const int lane = tid & 31;
    const int warp = tid >> 5;
    const int wm   = warp & 1;          // 2 warps along M (64 px each)
    const int wn   = warp >> 1;         // 4 warps along N (64 co each)

    const int tile = blockIdx.x;        // 896 = 32 images x 28 row-pairs
    const int b    = tile / 28;
    const int rp   = tile - b * 28;
    const int oh0  = 1 + 2 * rp;        // padded rows oh0, oh0+1
    const long q0  = GUARD + (long)b * (PG * PG) + (long)oh0 * PG;

    // ---- A-union: rows q0-65 .. q0+192 (258 vectors) ----
    {
        const int8_t* src0 = g_P + (q0 - 65) * 256;
        for (int i = tid; i < AU_ROWS * 16; i += 256) {
            const uint32_t row = i >> 4, g = i & 15;
            cpa16(Abase + row * 256 + swz(row, g) * 16, src0 + (size_t)row * 256 + g * 16);
        }
        asm volatile("cp.async.commit_group;" ::: "memory");
    }
    // ---- B tap 0 into buf 0 ----
    auto load_B = [&](int tap, int buf) {
        const int8_t* src0 = g_WB + (size_t)tap * (C_OUT * 256);
        const uint32_t dst0 = Bbase + buf * SM_B;
#pragma unroll
        for (int i = 0; i < 16; ++i) {
            const uint32_t u = tid + 256 * i;
            const uint32_t co = u >> 4, g = u & 15;
            cpa16(dst0 + co * 256 + swz(co, g) * 16, src0 + (size_t)co * 256 + g * 16);
        }
        asm volatile("cp.async.commit_group;" ::: "memory");
    };
    load_B(0, 0);

    int c[4][8][4];
#pragma unroll
    for (int i = 0; i < 4; ++i)
#pragma unroll
        for (int j = 0; j < 8; ++j)
#pragma unroll
            for (int k = 0; k < 4; ++k) c[i][j][k] = 0;

    // per-lane ldmatrix addressing constants
    const uint32_t aRow0 = 64u * wm + (lane & 15);     // + shift + 16*mi
    const uint32_t aKhi  = (uint32_t)(lane >> 4);      // 0/1 -> k granule +0/+1
    const uint32_t bCo0  = 64u * wn + (lane & 7) + ((lane >> 4) & 1) * 8;
    const uint32_t bKhi  = (uint32_t)((lane >> 3) & 1);

    for (int tap = 0; tap < 9; ++tap) {
        if (tap < 8) load_B(tap + 1, (tap + 1) & 1);
        if (tap < 8) asm volatile("cp.async.wait_group 1;" ::: "memory");
        else         asm volatile("cp.async.wait_group 0;" ::: "memory");
        __syncthreads();

        const uint32_t shift = (uint32_t)((tap / 3) * 64 + (tap % 3)); // union row offset
        const uint32_t Bcur  = Bbase + (tap & 1) * SM_B;

#pragma unroll
        for (int ks = 0; ks < 8; ++ks) {
            uint32_t a[4][4];
#pragma unroll
            for (int mi = 0; mi < 4; ++mi) {
                const uint32_t row = shift + aRow0 + 16u * mi;
                const uint32_t kg  = 2u * ks + aKhi;
                ldm4(a[mi][0], a[mi][1], a[mi][2], a[mi][3],
                     Abase + row * 256 + swz(row, kg) * 16);
            }
#pragma unroll
            for (int njp = 0; njp < 4; ++njp) {
                uint32_t bb[4];
                const uint32_t co = bCo0 + 16u * njp;
                const uint32_t kg = 2u * ks + bKhi;
                ldm4(bb[0], bb[1], bb[2], bb[3],
                     Bcur + co * 256 + swz(co, kg) * 16);
#pragma unroll
                for (int mi = 0; mi < 4; ++mi) {
                    mma8(c[mi][2 * njp],     a[mi], bb[0], bb[1]);
                    mma8(c[mi][2 * njp + 1], a[mi], bb[2], bb[3]);
                }
            }
        }
        __syncthreads();   // protect buf (tap&1) before it is reloaded at tap+2
    }

    // ---- epilogue: scale + direct stores (guard padding columns) ----
    float sa2[8][2];
#pragma unroll
    for (int nj = 0; nj < 8; ++nj) {
        const int co = 64 * wn + 8 * nj + (lane & 3) * 2;
        sa2[nj][0] = __ldg(&g_sa[co]);
        sa2[nj][1] = __ldg(&g_sa[co + 1]);
    }
    float* ob = out + (size_t)b * C_OUT * HW;

#pragma unroll
    for (int mi = 0; mi < 4; ++mi) {
#pragma unroll
        for (int rh = 0; rh < 2; ++rh) {
            const int m  = 64 * wm + 16 * mi + (lane >> 2) + 8 * rh;
            const int ow = m & 63;
            if (ow < 1 || ow > 56) continue;
            const int oh = oh0 + (m >> 6);
            const long poff = (long)(oh - 1) * WDIM + (ow - 1);
#pragma unroll
            for (int nj = 0; nj < 8; ++nj) {
                const int co = 64 * wn + 8 * nj + (lane & 3) * 2;
                const long o0 = (long)co * HW + poff;
                ob[o0]      = __int2float_rn(c[mi][nj][2 * rh])     * sa2[nj][0];
                ob[o0 + HW] = __int2float_rn(c[mi][nj][2 * rh + 1]) * sa2[nj][1];
            }
        }
    }
}

// ---------------------------------------------------------------------------
extern "C" void kernel_launch(void* const* d_in, const int* in_sizes, int n_in,
                              void* d_out, int out_size) {
    const float* x     = (const float*)d_in[0];
    const float* W     = (const float*)d_in[1];
    const float* RV    = (const float*)d_in[2];
    const float* alpha = (const float*)d_in[3];
    float* out         = (float*)d_out;

    cudaFuncSetAttribute(conv_mma,
                         cudaFuncAttributeMaxDynamicSharedMemorySize, SMEM_TOTAL);

    prep_weights<<<C_OUT, 256>>>(W, RV, alpha);
    pack_P<<<(NVEC + 255) / 256, 256>>>(x);
    conv_mma<<<BATCH * 28, 256, SMEM_TOTAL>>>(out);
}